// round 1
// baseline (speedup 1.0000x reference)
#include <cuda_runtime.h>
#include <cuda_bf16.h>
#include <math.h>

// Problem constants (fixed by the reference): B=4, N=512, D=4, H=256
#define BB 4
#define NN 512
#define DD 4
#define HH 256

// Scratch (allocation-free rule: __device__ globals)
__device__ float g_u[BB * NN * HH];    // x[b,j] @ W_e1[0:4]            (innode term, indexed by j)
__device__ float g_v[BB * NN * HH];    // x[b,i] @ W_e1[4:8] + b_e1     (outnode term, indexed by i)
__device__ float g_agg[BB * NN * HH];  // adjacency-aggregated edge features

// ---------------------------------------------------------------------------
// Kernel A: u[b,n,h], v[b,n,h]
// ---------------------------------------------------------------------------
__global__ void prep_uv_kernel(const float* __restrict__ x,
                               const float* __restrict__ W_e1,
                               const float* __restrict__ b_e1) {
    int idx = blockIdx.x * blockDim.x + threadIdx.x;   // over B*N*H
    if (idx >= BB * NN * HH) return;
    int h  = idx & (HH - 1);
    int bn = idx >> 8;
    const float* xr = x + bn * DD;
    float su = 0.0f;
    float sv = b_e1[h];
    #pragma unroll
    for (int d = 0; d < DD; d++) {
        float xv = xr[d];
        su += xv * W_e1[d * HH + h];
        sv += xv * W_e1[(DD + d) * HH + h];
    }
    g_u[idx] = su;
    g_v[idx] = sv;
}

// ---------------------------------------------------------------------------
// Kernel B: per (b,j):
//   agg[b,j,h'] = sum_i adj[b,i,j] * relu( relu(u_j + v_i) @ W_e2 + b_e2 )[h']
// One CTA per (b,j). 256 threads. C-tile 64(i) x 256(h'), microtile 4x16.
// ---------------------------------------------------------------------------
__global__ __launch_bounds__(256, 2)
void edge_gemm_kernel(const float* __restrict__ adj,
                      const float* __restrict__ W_e2,
                      const float* __restrict__ b_e2) {
    __shared__ float s_u[HH];           // u_j
    __shared__ float s_adj[NN];         // adj[:, j] for this b
    __shared__ float s_b2[HH];          // b_e2
    __shared__ float s_W[32 * 256];     // W_e2 k-slab [32][256]   (reused as reduction buf)
    __shared__ float s_A[64 * 33];      // relu(u_j + v_i) tile [64][32], padded

    const int bid = blockIdx.x;          // b*512 + j
    const int b   = bid >> 9;
    const int j   = bid & (NN - 1);
    const int tid = threadIdx.x;
    const int tx  = tid & 15;            // h' group (16 cols each)
    const int ty  = tid >> 4;            // i group  (4 rows each)

    s_u[tid]  = g_u[bid * HH + tid];
    s_b2[tid] = b_e2[tid];
    s_adj[tid]       = adj[(b * NN + tid)       * NN + j];
    s_adj[tid + 256] = adj[(b * NN + tid + 256) * NN + j];

    float partial[16];
    #pragma unroll
    for (int c = 0; c < 16; c++) partial[c] = 0.0f;

    const float* vb = g_v + b * NN * HH;

    for (int i0 = 0; i0 < NN; i0 += 64) {
        float acc[4][16];
        #pragma unroll
        for (int r = 0; r < 4; r++)
            #pragma unroll
            for (int c = 0; c < 16; c++) acc[r][c] = 0.0f;

        for (int k0 = 0; k0 < HH; k0 += 32) {
            __syncthreads();   // protect s_W / s_A from previous iteration's readers
            // Load W_e2 slab [32][256] (coalesced: consecutive tid -> consecutive h')
            #pragma unroll
            for (int m = 0; m < 32; m++)
                s_W[m * 256 + tid] = W_e2[(k0 + m) * HH + tid];
            // Build A tile: A[ii][kk] = relu(u_j[k0+kk] + v[i0+ii][k0+kk])
            #pragma unroll
            for (int q = 0; q < 8; q++) {
                int idx = q * 256 + tid;
                int ii  = idx >> 5;
                int kk  = idx & 31;
                float val = s_u[k0 + kk] + vb[(i0 + ii) * HH + (k0 + kk)];
                s_A[ii * 33 + kk] = fmaxf(val, 0.0f);
            }
            __syncthreads();

            #pragma unroll
            for (int kk = 0; kk < 32; kk++) {
                float a0 = s_A[(ty * 4 + 0) * 33 + kk];
                float a1 = s_A[(ty * 4 + 1) * 33 + kk];
                float a2 = s_A[(ty * 4 + 2) * 33 + kk];
                float a3 = s_A[(ty * 4 + 3) * 33 + kk];
                const float4* wrow = (const float4*)(s_W + kk * 256 + tx * 16);
                #pragma unroll
                for (int c4 = 0; c4 < 4; c4++) {
                    float4 w = wrow[c4];
                    acc[0][c4*4+0] += a0 * w.x; acc[0][c4*4+1] += a0 * w.y;
                    acc[0][c4*4+2] += a0 * w.z; acc[0][c4*4+3] += a0 * w.w;
                    acc[1][c4*4+0] += a1 * w.x; acc[1][c4*4+1] += a1 * w.y;
                    acc[1][c4*4+2] += a1 * w.z; acc[1][c4*4+3] += a1 * w.w;
                    acc[2][c4*4+0] += a2 * w.x; acc[2][c4*4+1] += a2 * w.y;
                    acc[2][c4*4+2] += a2 * w.z; acc[2][c4*4+3] += a2 * w.w;
                    acc[3][c4*4+0] += a3 * w.x; acc[3][c4*4+1] += a3 * w.y;
                    acc[3][c4*4+2] += a3 * w.z; acc[3][c4*4+3] += a3 * w.w;
                }
            }
        }

        // Epilogue for this i-tile: relu(+bias), adj-weight, accumulate over i
        #pragma unroll
        for (int r = 0; r < 4; r++) {
            float aw = s_adj[i0 + ty * 4 + r];
            #pragma unroll
            for (int c = 0; c < 16; c++) {
                float val = fmaxf(acc[r][c] + s_b2[tx * 16 + c], 0.0f);
                partial[c] += aw * val;
            }
        }
    }

    // Cross-thread reduction over the 16 ty-groups (reuse s_W as scratch)
    __syncthreads();
    float* red = s_W;
    #pragma unroll
    for (int c = 0; c < 16; c++) red[ty * 256 + tx * 16 + c] = partial[c];
    __syncthreads();
    float sum = 0.0f;
    #pragma unroll
    for (int t = 0; t < 16; t++) sum += red[t * 256 + tid];
    g_agg[bid * HH + tid] = sum;
}

// ---------------------------------------------------------------------------
// Kernel C: per-node MLP + log_softmax. 8 rows per CTA, 256 threads.
// ---------------------------------------------------------------------------
__global__ __launch_bounds__(256, 4)
void tail_kernel(const float* __restrict__ x,
                 const float* __restrict__ W_n1, const float* __restrict__ b_n1,
                 const float* __restrict__ W_n2, const float* __restrict__ b_n2,
                 const float* __restrict__ W_o1, const float* __restrict__ b_o1,
                 const float* __restrict__ W_o,  const float* __restrict__ b_o,
                 float* __restrict__ out) {
    __shared__ float sA[8][256];
    __shared__ float sB[8][256];
    __shared__ float sx[8][4];

    const int row0 = blockIdx.x * 8;          // row = b*N + n
    const int tid  = threadIdx.x;

    #pragma unroll
    for (int r = 0; r < 8; r++) sA[r][tid] = g_agg[(row0 + r) * HH + tid];
    if (tid < 32) sx[tid >> 2][tid & 3] = x[row0 * DD + tid];
    __syncthreads();

    // out1 = relu(agg @ W_n1 + b_n1)   sA -> sB
    {
        float acc[8];
        #pragma unroll
        for (int r = 0; r < 8; r++) acc[r] = b_n1[tid];
        #pragma unroll 4
        for (int k = 0; k < 256; k++) {
            float w = W_n1[k * 256 + tid];
            #pragma unroll
            for (int r = 0; r < 8; r++) acc[r] += sA[r][k] * w;
        }
        #pragma unroll
        for (int r = 0; r < 8; r++) sB[r][tid] = fmaxf(acc[r], 0.0f);
        __syncthreads();
    }

    // out2 = relu(out1 @ W_n2 + b_n2)  sB -> sA
    {
        float acc[8];
        #pragma unroll
        for (int r = 0; r < 8; r++) acc[r] = b_n2[tid];
        #pragma unroll 4
        for (int k = 0; k < 256; k++) {
            float w = W_n2[k * 256 + tid];
            #pragma unroll
            for (int r = 0; r < 8; r++) acc[r] += sB[r][k] * w;
        }
        __syncthreads();
        #pragma unroll
        for (int r = 0; r < 8; r++) sA[r][tid] = fmaxf(acc[r], 0.0f);
        __syncthreads();
    }

    // out4 = [x, out2] @ W_o1 + b_o1   (no relu)   -> sB
    {
        float acc[8];
        #pragma unroll
        for (int r = 0; r < 8; r++) acc[r] = b_o1[tid];
        #pragma unroll
        for (int d = 0; d < 4; d++) {
            float w = W_o1[d * 256 + tid];
            #pragma unroll
            for (int r = 0; r < 8; r++) acc[r] += sx[r][d] * w;
        }
        #pragma unroll 4
        for (int k = 0; k < 256; k++) {
            float w = W_o1[(4 + k) * 256 + tid];
            #pragma unroll
            for (int r = 0; r < 8; r++) acc[r] += sA[r][k] * w;
        }
        __syncthreads();
        #pragma unroll
        for (int r = 0; r < 8; r++) sB[r][tid] = acc[r];
        __syncthreads();
    }

    // out5 = out4 @ W_o + b_o ; log_softmax over D=4
    if (tid < 32) {
        int r = tid >> 2, d = tid & 3;
        float acc = b_o[d];
        #pragma unroll 4
        for (int h = 0; h < 256; h++) acc += sB[r][h] * W_o[h * 4 + d];
        float m = acc;
        m = fmaxf(m, __shfl_xor_sync(0xffffffffu, m, 1));
        m = fmaxf(m, __shfl_xor_sync(0xffffffffu, m, 2));
        float e = expf(acc - m);
        float s = e;
        s += __shfl_xor_sync(0xffffffffu, s, 1);
        s += __shfl_xor_sync(0xffffffffu, s, 2);
        out[(row0 + r) * 4 + d] = acc - m - logf(s);
    }
}

// ---------------------------------------------------------------------------
// Launch
// ---------------------------------------------------------------------------
extern "C" void kernel_launch(void* const* d_in, const int* in_sizes, int n_in,
                              void* d_out, int out_size) {
    const float* x    = (const float*)d_in[0];
    const float* adj  = (const float*)d_in[1];
    const float* W_e1 = (const float*)d_in[2];
    const float* b_e1 = (const float*)d_in[3];
    const float* W_e2 = (const float*)d_in[4];
    const float* b_e2 = (const float*)d_in[5];
    const float* W_n1 = (const float*)d_in[6];
    const float* b_n1 = (const float*)d_in[7];
    const float* W_n2 = (const float*)d_in[8];
    const float* b_n2 = (const float*)d_in[9];
    const float* W_o1 = (const float*)d_in[10];
    const float* b_o1 = (const float*)d_in[11];
    const float* W_o  = (const float*)d_in[12];
    const float* b_o  = (const float*)d_in[13];
    float* out = (float*)d_out;

    prep_uv_kernel<<<(BB * NN * HH) / 256, 256>>>(x, W_e1, b_e1);
    edge_gemm_kernel<<<BB * NN, 256>>>(adj, W_e2, b_e2);
    tail_kernel<<<(BB * NN) / 8, 256>>>(x, W_n1, b_n1, W_n2, b_n2,
                                        W_o1, b_o1, W_o, b_o, out);
}

// round 3
// speedup vs baseline: 5.4598x; 5.4598x over previous
#include <cuda_runtime.h>
#include <cuda_bf16.h>
#include <cstdint>
#include <math.h>

#define BB 4
#define NN 512
#define DD 4
#define HH 256

// ---------------------------------------------------------------------------
// Device scratch (allocation-free rule)
// ---------------------------------------------------------------------------
__device__ __align__(16) float g_u[BB * NN * HH];     // x[b,j] @ W_e1[0:4]
__device__ __align__(16) float g_v[BB * NN * HH];     // x[b,i] @ W_e1[4:8] + b_e1
__device__ __align__(16) float g_agg[BB * NN * HH];
__device__ __align__(16) float g_adjT[BB * NN * NN];  // adjT[b][j][i]
// W_e2 pre-packed into mma.sync B fragments:
// index [kstep s (16)][global n-tile g (32)][lane (32)] -> uint4{b0_hi,b1_hi,b0_lo,b1_lo}
__device__ __align__(16) uint4 g_Wf[16 * 32 * 32];

// ---------------------------------------------------------------------------
// PTX wrappers (all baseline sm_80-class instructions; compile for compute_103)
// ---------------------------------------------------------------------------
__device__ __forceinline__ uint32_t smem_to_u32(const void* p) {
    uint32_t a;
    asm("{ .reg .u64 t; cvta.to.shared.u64 t, %1; cvt.u32.u64 %0, t; }" : "=r"(a) : "l"(p));
    return a;
}

__device__ __forceinline__ void ldm4(uint32_t r[4], uint32_t addr) {
    asm volatile("ldmatrix.sync.aligned.m8n8.x4.shared.b16 {%0,%1,%2,%3}, [%4];"
                 : "=r"(r[0]), "=r"(r[1]), "=r"(r[2]), "=r"(r[3]) : "r"(addr));
}

__device__ __forceinline__ void mma_bf16(float c[4], const uint32_t a[4],
                                         uint32_t b0, uint32_t b1) {
    asm volatile(
        "mma.sync.aligned.m16n8k16.row.col.f32.bf16.bf16.f32 "
        "{%0,%1,%2,%3}, {%4,%5,%6,%7}, {%8,%9}, {%0,%1,%2,%3};"
        : "+f"(c[0]), "+f"(c[1]), "+f"(c[2]), "+f"(c[3])
        : "r"(a[0]), "r"(a[1]), "r"(a[2]), "r"(a[3]), "r"(b0), "r"(b1));
}

// ---------------------------------------------------------------------------
// Kernel A: u, v
// ---------------------------------------------------------------------------
__global__ void prep_uv_kernel(const float* __restrict__ x,
                               const float* __restrict__ W_e1,
                               const float* __restrict__ b_e1) {
    int idx = blockIdx.x * blockDim.x + threadIdx.x;
    if (idx >= BB * NN * HH) return;
    int h  = idx & (HH - 1);
    int bn = idx >> 8;
    const float* xr = x + bn * DD;
    float su = 0.0f;
    float sv = b_e1[h];
    #pragma unroll
    for (int d = 0; d < DD; d++) {
        float xv = xr[d];
        su += xv * W_e1[d * HH + h];
        sv += xv * W_e1[(DD + d) * HH + h];
    }
    g_u[idx] = su;
    g_v[idx] = sv;
}

// ---------------------------------------------------------------------------
// Kernel W: pack W_e2 (split bf16 hi/lo) into mma B-fragment layout
// ---------------------------------------------------------------------------
__global__ void wfrag_kernel(const float* __restrict__ W_e2) {
    int idx = blockIdx.x * blockDim.x + threadIdx.x;   // 16*32*32 = 16384
    if (idx >= 16 * 32 * 32) return;
    int t = idx & 31;
    int g = (idx >> 5) & 31;
    int s = idx >> 10;
    int n  = g * 8 + (t >> 2);
    int q  = t & 3;
    int k0 = s * 16 + q * 2;

    float w[4];
    w[0] = W_e2[(k0)     * HH + n];
    w[1] = W_e2[(k0 + 1) * HH + n];
    w[2] = W_e2[(k0 + 8) * HH + n];
    w[3] = W_e2[(k0 + 9) * HH + n];

    unsigned short hi[4], lo[4];
    #pragma unroll
    for (int e = 0; e < 4; e++) {
        __nv_bfloat16 h = __float2bfloat16_rn(w[e]);
        float r = w[e] - __bfloat162float(h);
        hi[e] = __bfloat16_as_ushort(h);
        lo[e] = __bfloat16_as_ushort(__float2bfloat16_rn(r));
    }
    uint4 o;
    o.x = (uint32_t)hi[0] | ((uint32_t)hi[1] << 16);   // b0_hi (k0, k0+1)
    o.y = (uint32_t)hi[2] | ((uint32_t)hi[3] << 16);   // b1_hi (k0+8, k0+9)
    o.z = (uint32_t)lo[0] | ((uint32_t)lo[1] << 16);   // b0_lo
    o.w = (uint32_t)lo[2] | ((uint32_t)lo[3] << 16);   // b1_lo
    g_Wf[idx] = o;
}

// ---------------------------------------------------------------------------
// Kernel T: transpose adj -> adjT[b][j][i]
// ---------------------------------------------------------------------------
__global__ void adjT_kernel(const float* __restrict__ adj) {
    __shared__ float t[32][33];
    int b = blockIdx.z;
    int i0 = blockIdx.y * 32, j0 = blockIdx.x * 32;
    t[threadIdx.y][threadIdx.x] =
        adj[((size_t)b * NN + i0 + threadIdx.y) * NN + j0 + threadIdx.x];
    __syncthreads();
    g_adjT[((size_t)b * NN + j0 + threadIdx.y) * NN + i0 + threadIdx.x] =
        t[threadIdx.x][threadIdx.y];
}

// ---------------------------------------------------------------------------
// Kernel E: per (b,j) edge GEMM on mma.sync (split bf16, 3 products),
//           fused bias+relu+adj-weighted i-reduction.
// 256 threads = 8 warps; each warp owns 32 h-cols; i processed in 16 tiles of 32.
// ---------------------------------------------------------------------------
#define ASTRIDE 264   // bf16 elems per A-tile row (16B-aligned rows, conflict-benign)

__global__ __launch_bounds__(256, 2)
void edge_mma_kernel(const float* __restrict__ b_e2) {
    __shared__ float s_u[HH];
    __shared__ float s_adj[NN];
    __shared__ __align__(16) unsigned short sAhi[32 * ASTRIDE];
    __shared__ __align__(16) unsigned short sAlo[32 * ASTRIDE];

    const int bid  = blockIdx.x;          // b*512 + j
    const int b    = bid >> 9;
    const int tid  = threadIdx.x;
    const int warp = tid >> 5;
    const int lane = tid & 31;
    const int q    = lane & 3;            // k-quad within fragment
    const int rg   = lane >> 2;           // row group / n within tile

    // Stage u_j and adj column
    s_u[tid] = g_u[bid * HH + tid];
    {
        const float* adjrow = g_adjT + ((size_t)b * NN + (bid & (NN - 1))) * NN;
        s_adj[tid]       = adjrow[tid];
        s_adj[tid + 256] = adjrow[tid + 256];
    }

    // Per-thread bias for the 8 output column slots
    float bias[8];
    #pragma unroll
    for (int c = 0; c < 8; c++)
        bias[c] = b_e2[warp * 32 + (c >> 1) * 8 + q * 2 + (c & 1)];

    float partial[8];
    #pragma unroll
    for (int c = 0; c < 8; c++) partial[c] = 0.0f;

    const uint32_t aHi = smem_to_u32(sAhi);
    const uint32_t aLo = smem_to_u32(sAlo);
    // ldmatrix per-lane offset: row = lane%16, col-half = lane/16
    const uint32_t offL = (uint32_t)(((lane & 15) * ASTRIDE + (lane >> 4) * 8) * 2);

    const float* vb = g_v + b * NN * HH;

    // Build-thread mapping: ii = tid/8 (row 0..31), kseg = (tid%8)*32
    const int ii   = tid >> 3;
    const int kseg = (tid & 7) * 32;

    #pragma unroll 1
    for (int iter = 0; iter < 16; iter++) {
        __syncthreads();   // previous iter's mma reads of sA done

        // ---- build A tile [32][256] hi/lo: relu(u + v) split to bf16 hi/lo ----
        {
            const float* vrow = vb + (iter * 32 + ii) * HH;
            #pragma unroll
            for (int g4 = 0; g4 < 8; g4++) {
                int k = kseg + g4 * 4;
                float4 v4 = *(const float4*)(vrow + k);
                float4 u4 = *(const float4*)(s_u + k);
                float f[4];
                f[0] = fmaxf(v4.x + u4.x, 0.0f);
                f[1] = fmaxf(v4.y + u4.y, 0.0f);
                f[2] = fmaxf(v4.z + u4.z, 0.0f);
                f[3] = fmaxf(v4.w + u4.w, 0.0f);
                unsigned short hs[4], ls[4];
                #pragma unroll
                for (int e = 0; e < 4; e++) {
                    __nv_bfloat16 h = __float2bfloat16_rn(f[e]);
                    float r = f[e] - __bfloat162float(h);
                    hs[e] = __bfloat16_as_ushort(h);
                    ls[e] = __bfloat16_as_ushort(__float2bfloat16_rn(r));
                }
                uint2 H, L;
                H.x = (uint32_t)hs[0] | ((uint32_t)hs[1] << 16);
                H.y = (uint32_t)hs[2] | ((uint32_t)hs[3] << 16);
                L.x = (uint32_t)ls[0] | ((uint32_t)ls[1] << 16);
                L.y = (uint32_t)ls[2] | ((uint32_t)ls[3] << 16);
                *(uint2*)(sAhi + ii * ASTRIDE + k) = H;
                *(uint2*)(sAlo + ii * ASTRIDE + k) = L;
            }
        }
        __syncthreads();

        // ---- mma over full K=256 ----
        float C[2][4][4];
        #pragma unroll
        for (int m = 0; m < 2; m++)
            #pragma unroll
            for (int j = 0; j < 4; j++)
                #pragma unroll
                for (int e = 0; e < 4; e++) C[m][j][e] = 0.0f;

        #pragma unroll 4
        for (int s = 0; s < 16; s++) {
            uint32_t ah0[4], ah1[4], al0[4], al1[4];
            uint32_t base = (uint32_t)(s * 32) + offL;
            ldm4(ah0, aHi + base);
            ldm4(ah1, aHi + base + 16 * ASTRIDE * 2);
            ldm4(al0, aLo + base);
            ldm4(al1, aLo + base + 16 * ASTRIDE * 2);
            #pragma unroll
            for (int j = 0; j < 4; j++) {
                uint4 wf = g_Wf[((s * 32) + warp * 4 + j) * 32 + lane];
                mma_bf16(C[0][j], ah0, wf.x, wf.y);   // hi*hi
                mma_bf16(C[1][j], ah1, wf.x, wf.y);
                mma_bf16(C[0][j], ah0, wf.z, wf.w);   // hi*lo
                mma_bf16(C[1][j], ah1, wf.z, wf.w);
                mma_bf16(C[0][j], al0, wf.x, wf.y);   // lo*hi
                mma_bf16(C[1][j], al1, wf.x, wf.y);
            }
        }

        // ---- epilogue: bias + relu, adj-weight, accumulate over i ----
        #pragma unroll
        for (int m = 0; m < 2; m++) {
            float a0 = s_adj[iter * 32 + m * 16 + rg];
            float a1 = s_adj[iter * 32 + m * 16 + rg + 8];
            #pragma unroll
            for (int j = 0; j < 4; j++) {
                partial[j*2+0] += a0 * fmaxf(C[m][j][0] + bias[j*2+0], 0.0f);
                partial[j*2+1] += a0 * fmaxf(C[m][j][1] + bias[j*2+1], 0.0f);
                partial[j*2+0] += a1 * fmaxf(C[m][j][2] + bias[j*2+0], 0.0f);
                partial[j*2+1] += a1 * fmaxf(C[m][j][3] + bias[j*2+1], 0.0f);
            }
        }
    }

    // ---- reduce over the 8 row-groups (lanes stride 4), write agg ----
    #pragma unroll
    for (int c = 0; c < 8; c++) {
        float v = partial[c];
        v += __shfl_down_sync(0xffffffffu, v, 16);
        v += __shfl_down_sync(0xffffffffu, v, 8);
        v += __shfl_down_sync(0xffffffffu, v, 4);
        partial[c] = v;
    }
    if (lane < 4) {
        #pragma unroll
        for (int c = 0; c < 8; c++)
            g_agg[bid * HH + warp * 32 + (c >> 1) * 8 + lane * 2 + (c & 1)] = partial[c];
    }
}

// ---------------------------------------------------------------------------
// Kernel C: per-node MLP + log_softmax
// ---------------------------------------------------------------------------
__global__ __launch_bounds__(256, 4)
void tail_kernel(const float* __restrict__ x,
                 const float* __restrict__ W_n1, const float* __restrict__ b_n1,
                 const float* __restrict__ W_n2, const float* __restrict__ b_n2,
                 const float* __restrict__ W_o1, const float* __restrict__ b_o1,
                 const float* __restrict__ W_o,  const float* __restrict__ b_o,
                 float* __restrict__ out) {
    __shared__ float sA[8][256];
    __shared__ float sB[8][256];
    __shared__ float sx[8][4];

    const int row0 = blockIdx.x * 8;
    const int tid  = threadIdx.x;

    #pragma unroll
    for (int r = 0; r < 8; r++) sA[r][tid] = g_agg[(row0 + r) * HH + tid];
    if (tid < 32) sx[tid >> 2][tid & 3] = x[row0 * DD + tid];
    __syncthreads();

    {
        float acc[8];
        #pragma unroll
        for (int r = 0; r < 8; r++) acc[r] = b_n1[tid];
        #pragma unroll 4
        for (int k = 0; k < 256; k++) {
            float wv = W_n1[k * 256 + tid];
            #pragma unroll
            for (int r = 0; r < 8; r++) acc[r] += sA[r][k] * wv;
        }
        #pragma unroll
        for (int r = 0; r < 8; r++) sB[r][tid] = fmaxf(acc[r], 0.0f);
        __syncthreads();
    }
    {
        float acc[8];
        #pragma unroll
        for (int r = 0; r < 8; r++) acc[r] = b_n2[tid];
        #pragma unroll 4
        for (int k = 0; k < 256; k++) {
            float wv = W_n2[k * 256 + tid];
            #pragma unroll
            for (int r = 0; r < 8; r++) acc[r] += sB[r][k] * wv;
        }
        __syncthreads();
        #pragma unroll
        for (int r = 0; r < 8; r++) sA[r][tid] = fmaxf(acc[r], 0.0f);
        __syncthreads();
    }
    {
        float acc[8];
        #pragma unroll
        for (int r = 0; r < 8; r++) acc[r] = b_o1[tid];
        #pragma unroll
        for (int d = 0; d < 4; d++) {
            float wv = W_o1[d * 256 + tid];
            #pragma unroll
            for (int r = 0; r < 8; r++) acc[r] += sx[r][d] * wv;
        }
        #pragma unroll 4
        for (int k = 0; k < 256; k++) {
            float wv = W_o1[(4 + k) * 256 + tid];
            #pragma unroll
            for (int r = 0; r < 8; r++) acc[r] += sA[r][k] * wv;
        }
        __syncthreads();
        #pragma unroll
        for (int r = 0; r < 8; r++) sB[r][tid] = acc[r];
        __syncthreads();
    }
    if (tid < 32) {
        int r = tid >> 2, d = tid & 3;
        float acc = b_o[d];
        #pragma unroll 4
        for (int h = 0; h < 256; h++) acc += sB[r][h] * W_o[h * 4 + d];
        float m = acc;
        m = fmaxf(m, __shfl_xor_sync(0xffffffffu, m, 1));
        m = fmaxf(m, __shfl_xor_sync(0xffffffffu, m, 2));
        float e = expf(acc - m);
        float s = e;
        s += __shfl_xor_sync(0xffffffffu, s, 1);
        s += __shfl_xor_sync(0xffffffffu, s, 2);
        out[(row0 + r) * 4 + d] = acc - m - logf(s);
    }
}

// ---------------------------------------------------------------------------
// Launch
// ---------------------------------------------------------------------------
extern "C" void kernel_launch(void* const* d_in, const int* in_sizes, int n_in,
                              void* d_out, int out_size) {
    const float* x    = (const float*)d_in[0];
    const float* adj  = (const float*)d_in[1];
    const float* W_e1 = (const float*)d_in[2];
    const float* b_e1 = (const float*)d_in[3];
    const float* W_e2 = (const float*)d_in[4];
    const float* b_e2 = (const float*)d_in[5];
    const float* W_n1 = (const float*)d_in[6];
    const float* b_n1 = (const float*)d_in[7];
    const float* W_n2 = (const float*)d_in[8];
    const float* b_n2 = (const float*)d_in[9];
    const float* W_o1 = (const float*)d_in[10];
    const float* b_o1 = (const float*)d_in[11];
    const float* W_o  = (const float*)d_in[12];
    const float* b_o  = (const float*)d_in[13];
    float* out = (float*)d_out;

    prep_uv_kernel<<<(BB * NN * HH) / 256, 256>>>(x, W_e1, b_e1);
    wfrag_kernel<<<64, 256>>>(W_e2);
    adjT_kernel<<<dim3(16, 16, 4), dim3(32, 32)>>>(adj);
    edge_mma_kernel<<<BB * NN, 256>>>(b_e2);
    tail_kernel<<<(BB * NN) / 8, 256>>>(x, W_n1, b_n1, W_n2, b_n2,
                                        W_o1, b_o1, W_o, b_o, out);
}

// round 4
// speedup vs baseline: 11.9998x; 2.1978x over previous
#include <cuda_runtime.h>
#include <cuda_bf16.h>
#include <cuda_fp16.h>
#include <cstdint>
#include <math.h>

#define BB 4
#define NN 512
#define DD 4
#define HH 256

// ---------------------------------------------------------------------------
// Device scratch (allocation-free rule)
// ---------------------------------------------------------------------------
__device__ __align__(16) float g_u[BB * NN * HH];     // x[b,j] @ W_e1[0:4]
__device__ __align__(16) float g_v[BB * NN * HH];     // x[b,i] @ W_e1[4:8] + b_e1
__device__ __align__(16) float g_agg[BB * NN * HH];
__device__ __align__(16) float g_adjT[BB * NN * NN];  // adjT[b][j][i]
// W_e2 fp16, packed into mma.sync B fragments, two k-steps per uint4:
// [t(8)][g(32)][lane(32)] -> uint4{ b0(s=2t), b1(s=2t), b0(s=2t+1), b1(s=2t+1) }
__device__ __align__(16) uint4 g_Wh[8 * 32 * 32];

// ---------------------------------------------------------------------------
// PTX wrappers (baseline sm_80-class; compile clean for compute_103)
// ---------------------------------------------------------------------------
__device__ __forceinline__ uint32_t smem_to_u32(const void* p) {
    uint32_t a;
    asm("{ .reg .u64 t; cvta.to.shared.u64 t, %1; cvt.u32.u64 %0, t; }" : "=r"(a) : "l"(p));
    return a;
}

__device__ __forceinline__ void ldm4(uint32_t r[4], uint32_t addr) {
    asm volatile("ldmatrix.sync.aligned.m8n8.x4.shared.b16 {%0,%1,%2,%3}, [%4];"
                 : "=r"(r[0]), "=r"(r[1]), "=r"(r[2]), "=r"(r[3]) : "r"(addr));
}

__device__ __forceinline__ void mma_f16(float c[4], const uint32_t a[4],
                                        uint32_t b0, uint32_t b1) {
    asm volatile(
        "mma.sync.aligned.m16n8k16.row.col.f32.f16.f16.f32 "
        "{%0,%1,%2,%3}, {%4,%5,%6,%7}, {%8,%9}, {%0,%1,%2,%3};"
        : "+f"(c[0]), "+f"(c[1]), "+f"(c[2]), "+f"(c[3])
        : "r"(a[0]), "r"(a[1]), "r"(a[2]), "r"(a[3]), "r"(b0), "r"(b1));
}

__device__ __forceinline__ uint32_t pack_h2(float a, float b) {
    __half2 h = __floats2half2_rn(a, b);
    return *(uint32_t*)&h;
}

// ---------------------------------------------------------------------------
// Kernel A: u, v
// ---------------------------------------------------------------------------
__global__ void prep_uv_kernel(const float* __restrict__ x,
                               const float* __restrict__ W_e1,
                               const float* __restrict__ b_e1) {
    int idx = blockIdx.x * blockDim.x + threadIdx.x;
    if (idx >= BB * NN * HH) return;
    int h  = idx & (HH - 1);
    int bn = idx >> 8;
    const float* xr = x + bn * DD;
    float su = 0.0f;
    float sv = b_e1[h];
    #pragma unroll
    for (int d = 0; d < DD; d++) {
        float xv = xr[d];
        su += xv * W_e1[d * HH + h];
        sv += xv * W_e1[(DD + d) * HH + h];
    }
    g_u[idx] = su;
    g_v[idx] = sv;
}

// ---------------------------------------------------------------------------
// Kernel W: pack W_e2 (fp16) into mma B-fragment layout, 2 k-steps per uint4
// ---------------------------------------------------------------------------
__global__ void wfrag_kernel(const float* __restrict__ W_e2) {
    int idx = blockIdx.x * blockDim.x + threadIdx.x;   // 8*32*32 = 8192
    if (idx >= 8 * 32 * 32) return;
    int lane = idx & 31;
    int g    = (idx >> 5) & 31;
    int t    = idx >> 10;
    int n  = g * 8 + (lane >> 2);
    int q  = lane & 3;
    int k0 = (2 * t) * 16 + q * 2;       // s even
    int k1 = (2 * t + 1) * 16 + q * 2;   // s odd

    uint4 o;
    o.x = pack_h2(W_e2[(k0)     * HH + n], W_e2[(k0 + 1) * HH + n]);
    o.y = pack_h2(W_e2[(k0 + 8) * HH + n], W_e2[(k0 + 9) * HH + n]);
    o.z = pack_h2(W_e2[(k1)     * HH + n], W_e2[(k1 + 1) * HH + n]);
    o.w = pack_h2(W_e2[(k1 + 8) * HH + n], W_e2[(k1 + 9) * HH + n]);
    g_Wh[idx] = o;
}

// ---------------------------------------------------------------------------
// Kernel T: transpose adj -> adjT[b][j][i]
// ---------------------------------------------------------------------------
__global__ void adjT_kernel(const float* __restrict__ adj) {
    __shared__ float t[32][33];
    int b = blockIdx.z;
    int i0 = blockIdx.y * 32, j0 = blockIdx.x * 32;
    t[threadIdx.y][threadIdx.x] =
        adj[((size_t)b * NN + i0 + threadIdx.y) * NN + j0 + threadIdx.x];
    __syncthreads();
    g_adjT[((size_t)b * NN + j0 + threadIdx.y) * NN + i0 + threadIdx.x] =
        t[threadIdx.x][threadIdx.y];
}

// ---------------------------------------------------------------------------
// Kernel E: per (b,j) edge GEMM (fp16 mma, single product),
//           fused bias+relu+adj-weighted i-reduction.
// 8 warps = 2(M-halves of a 64-row i-tile) x 4(N-groups of 64 cols).
// A tile in SMEM: 64 rows x 256 fp16, XOR-swizzled (c ^= row&7 on 16B chunks).
// ---------------------------------------------------------------------------
__global__ __launch_bounds__(256, 2)
void edge_mma_kernel(const float* __restrict__ b_e2) {
    __shared__ float s_u[HH];
    __shared__ float s_b2[HH];
    __shared__ float s_adj[NN];
    __shared__ __align__(16) __half sA[64 * 256];
    __shared__ float sred[4][4][16];

    const int bid  = blockIdx.x;          // b*512 + j
    const int b    = bid >> 9;
    const int tid  = threadIdx.x;
    const int warp = tid >> 5;
    const int lane = tid & 31;
    const int warp_m = warp & 1;          // 32-row half of the 64-row tile
    const int warp_n = warp >> 1;         // 64-col group
    const int rg = lane >> 2;
    const int q  = lane & 3;
    const int hi4 = lane >> 4;

    s_u[tid]  = g_u[bid * HH + tid];
    s_b2[tid] = b_e2[tid];
    {
        const float* adjrow = g_adjT + ((size_t)b * NN + (bid & (NN - 1))) * NN;
        s_adj[tid]       = adjrow[tid];
        s_adj[tid + 256] = adjrow[tid + 256];
    }

    const uint32_t aBase = smem_to_u32(sA);
    const int rowA = warp_m * 32 + (lane & 15);
    const uint32_t swb = (uint32_t)(rowA & 7);
    const uint32_t base0 = aBase + rowA * 512;
    const uint32_t base1 = base0 + 16 * 512;

    // build mapping: row ii, k-chunk of 64 elems
    const int ii = tid & 63;
    const int kb = tid >> 6;
    const float* vb = g_v + b * NN * HH;

    float partial[16];
    #pragma unroll
    for (int c = 0; c < 16; c++) partial[c] = 0.0f;

    #pragma unroll 1
    for (int iter = 0; iter < 8; iter++) {
        __syncthreads();   // prior iter's ldmatrix done (and iter0: s_u ready)

        // ---- build A tile: relu(u_j + v_i) -> fp16, swizzled ----
        {
            const float* vrow = vb + (iter * 64 + ii) * HH + kb * 64;
            const float* urow = s_u + kb * 64;
            #pragma unroll
            for (int p = 0; p < 8; p++) {
                float4 v0 = *(const float4*)(vrow + p * 8);
                float4 v1 = *(const float4*)(vrow + p * 8 + 4);
                float4 u0 = *(const float4*)(urow + p * 8);
                float4 u1 = *(const float4*)(urow + p * 8 + 4);
                uint4 o;
                o.x = pack_h2(fmaxf(v0.x + u0.x, 0.0f), fmaxf(v0.y + u0.y, 0.0f));
                o.y = pack_h2(fmaxf(v0.z + u0.z, 0.0f), fmaxf(v0.w + u0.w, 0.0f));
                o.z = pack_h2(fmaxf(v1.x + u1.x, 0.0f), fmaxf(v1.y + u1.y, 0.0f));
                o.w = pack_h2(fmaxf(v1.z + u1.z, 0.0f), fmaxf(v1.w + u1.w, 0.0f));
                int c = kb * 8 + p;
                *(uint4*)((char*)sA + ii * 512 + ((c ^ (ii & 7)) << 4)) = o;
            }
        }
        __syncthreads();

        // ---- mma: warp computes rows [warp_m*32, +32) x cols [warp_n*64, +64) ----
        float C[2][8][4];
        #pragma unroll
        for (int m = 0; m < 2; m++)
            #pragma unroll
            for (int j = 0; j < 8; j++)
                #pragma unroll
                for (int e = 0; e < 4; e++) C[m][j][e] = 0.0f;

        #pragma unroll 2
        for (int t = 0; t < 8; t++) {
            uint32_t f00[4], f01[4], f10[4], f11[4];
            uint32_t c0 = (uint32_t)(4 * t + hi4);
            ldm4(f00, base0 + (((c0)     ^ swb) << 4));
            ldm4(f01, base0 + (((c0 + 2) ^ swb) << 4));
            ldm4(f10, base1 + (((c0)     ^ swb) << 4));
            ldm4(f11, base1 + (((c0 + 2) ^ swb) << 4));
            const uint4* wp = g_Wh + ((t * 32) + warp_n * 8) * 32 + lane;
            #pragma unroll
            for (int j = 0; j < 8; j++) {
                uint4 wf = wp[j * 32];
                mma_f16(C[0][j], f00, wf.x, wf.y);
                mma_f16(C[1][j], f10, wf.x, wf.y);
                mma_f16(C[0][j], f01, wf.z, wf.w);
                mma_f16(C[1][j], f11, wf.z, wf.w);
            }
        }

        // ---- epilogue: bias + relu, adj-weight, accumulate over i ----
        const int ir = iter * 64 + warp_m * 32;
        #pragma unroll
        for (int m = 0; m < 2; m++) {
            float a0 = s_adj[ir + m * 16 + rg];
            float a1 = s_adj[ir + m * 16 + rg + 8];
            #pragma unroll
            for (int j = 0; j < 8; j++) {
                float bb0 = s_b2[warp_n * 64 + j * 8 + q * 2];
                float bb1 = s_b2[warp_n * 64 + j * 8 + q * 2 + 1];
                partial[j*2+0] += a0 * fmaxf(C[m][j][0] + bb0, 0.0f)
                                + a1 * fmaxf(C[m][j][2] + bb0, 0.0f);
                partial[j*2+1] += a0 * fmaxf(C[m][j][1] + bb1, 0.0f)
                                + a1 * fmaxf(C[m][j][3] + bb1, 0.0f);
            }
        }
    }

    // ---- reduce over the 8 row-groups within each warp ----
    #pragma unroll
    for (int c = 0; c < 16; c++) {
        float v = partial[c];
        v += __shfl_down_sync(0xffffffffu, v, 16);
        v += __shfl_down_sync(0xffffffffu, v, 8);
        v += __shfl_down_sync(0xffffffffu, v, 4);
        partial[c] = v;
    }
    // ---- combine warp_m pair via smem, write agg ----
    if (warp_m == 1 && lane < 4) {
        #pragma unroll
        for (int c = 0; c < 16; c++) sred[warp_n][lane][c] = partial[c];
    }
    __syncthreads();
    if (warp_m == 0 && lane < 4) {
        #pragma unroll
        for (int c = 0; c < 16; c++) {
            float v = partial[c] + sred[warp_n][lane][c];
            int col = warp_n * 64 + (c >> 1) * 8 + lane * 2 + (c & 1);
            g_agg[bid * HH + col] = v;
        }
    }
}

// ---------------------------------------------------------------------------
// Kernel C: per-node MLP + log_softmax
// ---------------------------------------------------------------------------
__global__ __launch_bounds__(256, 4)
void tail_kernel(const float* __restrict__ x,
                 const float* __restrict__ W_n1, const float* __restrict__ b_n1,
                 const float* __restrict__ W_n2, const float* __restrict__ b_n2,
                 const float* __restrict__ W_o1, const float* __restrict__ b_o1,
                 const float* __restrict__ W_o,  const float* __restrict__ b_o,
                 float* __restrict__ out) {
    __shared__ float sA[8][256];
    __shared__ float sB[8][256];
    __shared__ float sx[8][4];

    const int row0 = blockIdx.x * 8;
    const int tid  = threadIdx.x;

    #pragma unroll
    for (int r = 0; r < 8; r++) sA[r][tid] = g_agg[(row0 + r) * HH + tid];
    if (tid < 32) sx[tid >> 2][tid & 3] = x[row0 * DD + tid];
    __syncthreads();

    {
        float acc[8];
        #pragma unroll
        for (int r = 0; r < 8; r++) acc[r] = b_n1[tid];
        #pragma unroll 4
        for (int k = 0; k < 256; k++) {
            float wv = W_n1[k * 256 + tid];
            #pragma unroll
            for (int r = 0; r < 8; r++) acc[r] += sA[r][k] * wv;
        }
        #pragma unroll
        for (int r = 0; r < 8; r++) sB[r][tid] = fmaxf(acc[r], 0.0f);
        __syncthreads();
    }
    {
        float acc[8];
        #pragma unroll
        for (int r = 0; r < 8; r++) acc[r] = b_n2[tid];
        #pragma unroll 4
        for (int k = 0; k < 256; k++) {
            float wv = W_n2[k * 256 + tid];
            #pragma unroll
            for (int r = 0; r < 8; r++) acc[r] += sB[r][k] * wv;
        }
        __syncthreads();
        #pragma unroll
        for (int r = 0; r < 8; r++) sA[r][tid] = fmaxf(acc[r], 0.0f);
        __syncthreads();
    }
    {
        float acc[8];
        #pragma unroll
        for (int r = 0; r < 8; r++) acc[r] = b_o1[tid];
        #pragma unroll
        for (int d = 0; d < 4; d++) {
            float wv = W_o1[d * 256 + tid];
            #pragma unroll
            for (int r = 0; r < 8; r++) acc[r] += sx[r][d] * wv;
        }
        #pragma unroll 4
        for (int k = 0; k < 256; k++) {
            float wv = W_o1[(4 + k) * 256 + tid];
            #pragma unroll
            for (int r = 0; r < 8; r++) acc[r] += sA[r][k] * wv;
        }
        __syncthreads();
        #pragma unroll
        for (int r = 0; r < 8; r++) sB[r][tid] = acc[r];
        __syncthreads();
    }
    if (tid < 32) {
        int r = tid >> 2, d = tid & 3;
        float acc = b_o[d];
        #pragma unroll 4
        for (int h = 0; h < 256; h++) acc += sB[r][h] * W_o[h * 4 + d];
        float m = acc;
        m = fmaxf(m, __shfl_xor_sync(0xffffffffu, m, 1));
        m = fmaxf(m, __shfl_xor_sync(0xffffffffu, m, 2));
        float e = expf(acc - m);
        float s = e;
        s += __shfl_xor_sync(0xffffffffu, s, 1);
        s += __shfl_xor_sync(0xffffffffu, s, 2);
        out[(row0 + r) * 4 + d] = acc - m - logf(s);
    }
}

// ---------------------------------------------------------------------------
// Launch
// ---------------------------------------------------------------------------
extern "C" void kernel_launch(void* const* d_in, const int* in_sizes, int n_in,
                              void* d_out, int out_size) {
    const float* x    = (const float*)d_in[0];
    const float* adj  = (const float*)d_in[1];
    const float* W_e1 = (const float*)d_in[2];
    const float* b_e1 = (const float*)d_in[3];
    const float* W_e2 = (const float*)d_in[4];
    const float* b_e2 = (const float*)d_in[5];
    const float* W_n1 = (const float*)d_in[6];
    const float* b_n1 = (const float*)d_in[7];
    const float* W_n2 = (const float*)d_in[8];
    const float* b_n2 = (const float*)d_in[9];
    const float* W_o1 = (const float*)d_in[10];
    const float* b_o1 = (const float*)d_in[11];
    const float* W_o  = (const float*)d_in[12];
    const float* b_o  = (const float*)d_in[13];
    float* out = (float*)d_out;

    prep_uv_kernel<<<(BB * NN * HH) / 256, 256>>>(x, W_e1, b_e1);
    wfrag_kernel<<<32, 256>>>(W_e2);
    adjT_kernel<<<dim3(16, 16, 4), dim3(32, 32)>>>(adj);
    edge_mma_kernel<<<BB * NN, 256>>>(b_e2);
    tail_kernel<<<(BB * NN) / 8, 256>>>(x, W_n1, b_n1, W_n2, b_n2,
                                        W_o1, b_o1, W_o, b_o, out);
}

// round 5
// speedup vs baseline: 12.2225x; 1.0186x over previous
#include <cuda_runtime.h>
#include <cuda_bf16.h>
#include <cuda_fp16.h>
#include <cstdint>
#include <math.h>

#define BB 4
#define NN 512
#define DD 4
#define HH 256

// ---------------------------------------------------------------------------
// Device scratch (allocation-free rule)
// ---------------------------------------------------------------------------
__device__ __align__(16) float g_u[BB * NN * HH];     // x[b,j] @ W_e1[0:4]
__device__ __align__(16) float g_v[BB * NN * HH];     // x[b,i] @ W_e1[4:8] + b_e1
__device__ __align__(16) float g_agg[BB * NN * HH];
__device__ __align__(16) float g_adjT[BB * NN * NN];  // adjT[b][j][i]
// W_e2 fp16, mma B-fragments, two k-steps per uint4:
// [t(8)][g(32)][lane(32)] -> uint4{ b0(s=2t), b1(s=2t), b0(s=2t+1), b1(s=2t+1) }
__device__ __align__(16) uint4 g_Wh[8 * 32 * 32];

// ---------------------------------------------------------------------------
// PTX wrappers (baseline sm_80-class; compile clean for compute_103)
// ---------------------------------------------------------------------------
__device__ __forceinline__ uint32_t smem_to_u32(const void* p) {
    uint32_t a;
    asm("{ .reg .u64 t; cvta.to.shared.u64 t, %1; cvt.u32.u64 %0, t; }" : "=r"(a) : "l"(p));
    return a;
}

__device__ __forceinline__ void ldm4(uint32_t r[4], uint32_t addr) {
    asm volatile("ldmatrix.sync.aligned.m8n8.x4.shared.b16 {%0,%1,%2,%3}, [%4];"
                 : "=r"(r[0]), "=r"(r[1]), "=r"(r[2]), "=r"(r[3]) : "r"(addr));
}

__device__ __forceinline__ void mma_f16(float c[4], const uint32_t a[4],
                                        uint32_t b0, uint32_t b1) {
    asm volatile(
        "mma.sync.aligned.m16n8k16.row.col.f32.f16.f16.f32 "
        "{%0,%1,%2,%3}, {%4,%5,%6,%7}, {%8,%9}, {%0,%1,%2,%3};"
        : "+f"(c[0]), "+f"(c[1]), "+f"(c[2]), "+f"(c[3])
        : "r"(a[0]), "r"(a[1]), "r"(a[2]), "r"(a[3]), "r"(b0), "r"(b1));
}

__device__ __forceinline__ uint32_t pack_h2(float a, float b) {
    __half2 h = __floats2half2_rn(a, b);
    return *(uint32_t*)&h;
}

// ---------------------------------------------------------------------------
// Kernel A: u, v
// ---------------------------------------------------------------------------
__global__ void prep_uv_kernel(const float* __restrict__ x,
                               const float* __restrict__ W_e1,
                               const float* __restrict__ b_e1) {
    int idx = blockIdx.x * blockDim.x + threadIdx.x;
    if (idx >= BB * NN * HH) return;
    int h  = idx & (HH - 1);
    int bn = idx >> 8;
    const float* xr = x + bn * DD;
    float su = 0.0f;
    float sv = b_e1[h];
    #pragma unroll
    for (int d = 0; d < DD; d++) {
        float xv = xr[d];
        su += xv * W_e1[d * HH + h];
        sv += xv * W_e1[(DD + d) * HH + h];
    }
    g_u[idx] = su;
    g_v[idx] = sv;
}

// ---------------------------------------------------------------------------
// Kernel W: pack W_e2 (fp16) into mma B-fragment layout, 2 k-steps per uint4
// ---------------------------------------------------------------------------
__global__ void wfrag_kernel(const float* __restrict__ W_e2) {
    int idx = blockIdx.x * blockDim.x + threadIdx.x;   // 8*32*32 = 8192
    if (idx >= 8 * 32 * 32) return;
    int lane = idx & 31;
    int g    = (idx >> 5) & 31;
    int t    = idx >> 10;
    int n  = g * 8 + (lane >> 2);
    int q  = lane & 3;
    int k0 = (2 * t) * 16 + q * 2;       // s even
    int k1 = (2 * t + 1) * 16 + q * 2;   // s odd

    uint4 o;
    o.x = pack_h2(W_e2[(k0)     * HH + n], W_e2[(k0 + 1) * HH + n]);
    o.y = pack_h2(W_e2[(k0 + 8) * HH + n], W_e2[(k0 + 9) * HH + n]);
    o.z = pack_h2(W_e2[(k1)     * HH + n], W_e2[(k1 + 1) * HH + n]);
    o.w = pack_h2(W_e2[(k1 + 8) * HH + n], W_e2[(k1 + 9) * HH + n]);
    g_Wh[idx] = o;
}

// ---------------------------------------------------------------------------
// Kernel T: transpose adj -> adjT[b][j][i]
// ---------------------------------------------------------------------------
__global__ void adjT_kernel(const float* __restrict__ adj) {
    __shared__ float t[32][33];
    int b = blockIdx.z;
    int i0 = blockIdx.y * 32, j0 = blockIdx.x * 32;
    t[threadIdx.y][threadIdx.x] =
        adj[((size_t)b * NN + i0 + threadIdx.y) * NN + j0 + threadIdx.x];
    __syncthreads();
    g_adjT[((size_t)b * NN + j0 + threadIdx.y) * NN + i0 + threadIdx.x] =
        t[threadIdx.x][threadIdx.y];
}

// ---------------------------------------------------------------------------
// Kernel E: per (b,j) edge GEMM, fused bias+relu+adj-weighted i-reduction.
// 128 threads = 4 warps. Warp tile: 64(M, full i-tile) x 64(N). 8 i-iters.
// Each warp owns disjoint output columns for ALL rows -> no cross-warp reduce.
// A tile: 64 x 256 fp16, XOR-swizzled (16B chunk index c ^= row&7).
// ---------------------------------------------------------------------------
__global__ __launch_bounds__(128, 2)
void edge_mma_kernel(const float* __restrict__ b_e2) {
    __shared__ float s_u[HH];
    __shared__ float s_b2[HH];
    __shared__ float s_adj[NN];
    __shared__ __align__(16) __half sA[64 * 256];

    const int bid  = blockIdx.x;          // b*512 + j
    const int b    = bid >> 9;
    const int tid  = threadIdx.x;
    const int warp = tid >> 5;            // owns cols [warp*64, +64)
    const int lane = tid & 31;
    const int rg   = lane >> 2;
    const int q    = lane & 3;
    const int hi4  = lane >> 4;

    s_u[tid]        = g_u[bid * HH + tid];
    s_u[tid + 128]  = g_u[bid * HH + tid + 128];
    s_b2[tid]       = b_e2[tid];
    s_b2[tid + 128] = b_e2[tid + 128];
    {
        const float* adjrow = g_adjT + ((size_t)b * NN + (bid & (NN - 1))) * NN;
        #pragma unroll
        for (int p = 0; p < 4; p++) s_adj[tid + p * 128] = adjrow[tid + p * 128];
    }

    const uint32_t aBase = smem_to_u32(sA);
    const uint32_t swb   = (uint32_t)(lane & 7);
    // per-m-tile row base: row = m*16 + (lane&15)
    const uint32_t rbase = aBase + (uint32_t)(lane & 15) * 512;

    // build mapping: row ii = tid>>1, 128-col half kb
    const int ii = tid >> 1;
    const int kb = (tid & 1) * 128;
    const float* vb = g_v + b * NN * HH;

    float partial[16];
    #pragma unroll
    for (int c = 0; c < 16; c++) partial[c] = 0.0f;

    #pragma unroll 1
    for (int iter = 0; iter < 8; iter++) {
        __syncthreads();   // prior iter's ldmatrix reads done

        // ---- build A tile [64][256]: relu(u_j + v_i) -> fp16, swizzled ----
        {
            const float* vrow = vb + (iter * 64 + ii) * HH + kb;
            const float* urow = s_u + kb;
            #pragma unroll
            for (int p = 0; p < 16; p++) {
                float4 v0 = *(const float4*)(vrow + p * 8);
                float4 v1 = *(const float4*)(vrow + p * 8 + 4);
                float4 u0 = *(const float4*)(urow + p * 8);
                float4 u1 = *(const float4*)(urow + p * 8 + 4);
                uint4 o;
                o.x = pack_h2(fmaxf(v0.x + u0.x, 0.0f), fmaxf(v0.y + u0.y, 0.0f));
                o.y = pack_h2(fmaxf(v0.z + u0.z, 0.0f), fmaxf(v0.w + u0.w, 0.0f));
                o.z = pack_h2(fmaxf(v1.x + u1.x, 0.0f), fmaxf(v1.y + u1.y, 0.0f));
                o.w = pack_h2(fmaxf(v1.z + u1.z, 0.0f), fmaxf(v1.w + u1.w, 0.0f));
                int c = (kb >> 3) + p;    // 16B-chunk index 0..31
                *(uint4*)((char*)sA + ii * 512 + ((c ^ (ii & 7)) << 4)) = o;
            }
        }
        __syncthreads();

        // ---- mma: this warp computes rows [0,64) x cols [warp*64, +64) ----
        float C[4][8][4];
        #pragma unroll
        for (int m = 0; m < 4; m++)
            #pragma unroll
            for (int j = 0; j < 8; j++)
                #pragma unroll
                for (int e = 0; e < 4; e++) C[m][j][e] = 0.0f;

        #pragma unroll 1
        for (int t = 0; t < 8; t++) {
            // A fragments for ksteps 2t (a0) and 2t+1 (a1), 4 m-tiles of 16 rows
            uint32_t a0[4][4], a1[4][4];
            uint32_t c0 = (uint32_t)(4 * t + hi4);
            #pragma unroll
            for (int m = 0; m < 4; m++) {
                uint32_t rb = rbase + (uint32_t)(m * 16) * 512;
                ldm4(a0[m], rb + (((c0)     ^ swb) << 4));
                ldm4(a1[m], rb + (((c0 + 2) ^ swb) << 4));
            }
            const uint4* wp = g_Wh + ((t * 32) + warp * 8) * 32 + lane;
            #pragma unroll
            for (int j = 0; j < 8; j++) {
                uint4 wf = wp[j * 32];
                #pragma unroll
                for (int m = 0; m < 4; m++) {
                    mma_f16(C[m][j], a0[m], wf.x, wf.y);
                    mma_f16(C[m][j], a1[m], wf.z, wf.w);
                }
            }
        }

        // ---- epilogue: bias + relu, adj-weight, accumulate over i ----
        #pragma unroll
        for (int m = 0; m < 4; m++) {
            float aw0 = s_adj[iter * 64 + m * 16 + rg];
            float aw1 = s_adj[iter * 64 + m * 16 + rg + 8];
            #pragma unroll
            for (int j = 0; j < 8; j++) {
                float bb0 = s_b2[warp * 64 + j * 8 + q * 2];
                float bb1 = s_b2[warp * 64 + j * 8 + q * 2 + 1];
                partial[j*2+0] += aw0 * fmaxf(C[m][j][0] + bb0, 0.0f)
                                + aw1 * fmaxf(C[m][j][2] + bb0, 0.0f);
                partial[j*2+1] += aw0 * fmaxf(C[m][j][1] + bb1, 0.0f)
                                + aw1 * fmaxf(C[m][j][3] + bb1, 0.0f);
            }
        }
    }

    // ---- reduce over 8 row-groups (lanes stride 4); lanes 0-3 write ----
    #pragma unroll
    for (int c = 0; c < 16; c++) {
        float v = partial[c];
        v += __shfl_down_sync(0xffffffffu, v, 16);
        v += __shfl_down_sync(0xffffffffu, v, 8);
        v += __shfl_down_sync(0xffffffffu, v, 4);
        partial[c] = v;
    }
    if (lane < 4) {
        #pragma unroll
        for (int c = 0; c < 16; c++) {
            int col = warp * 64 + (c >> 1) * 8 + lane * 2 + (c & 1);
            g_agg[bid * HH + col] = partial[c];
        }
    }
}

// ---------------------------------------------------------------------------
// Kernel C: per-node MLP + log_softmax
// ---------------------------------------------------------------------------
__global__ __launch_bounds__(256, 4)
void tail_kernel(const float* __restrict__ x,
                 const float* __restrict__ W_n1, const float* __restrict__ b_n1,
                 const float* __restrict__ W_n2, const float* __restrict__ b_n2,
                 const float* __restrict__ W_o1, const float* __restrict__ b_o1,
                 const float* __restrict__ W_o,  const float* __restrict__ b_o,
                 float* __restrict__ out) {
    __shared__ float sA[8][256];
    __shared__ float sB[8][256];
    __shared__ float sx[8][4];

    const int row0 = blockIdx.x * 8;
    const int tid  = threadIdx.x;

    #pragma unroll
    for (int r = 0; r < 8; r++) sA[r][tid] = g_agg[(row0 + r) * HH + tid];
    if (tid < 32) sx[tid >> 2][tid & 3] = x[row0 * DD + tid];
    __syncthreads();

    {
        float acc[8];
        #pragma unroll
        for (int r = 0; r < 8; r++) acc[r] = b_n1[tid];
        #pragma unroll 4
        for (int k = 0; k < 256; k++) {
            float wv = W_n1[k * 256 + tid];
            #pragma unroll
            for (int r = 0; r < 8; r++) acc[r] += sA[r][k] * wv;
        }
        #pragma unroll
        for (int r = 0; r < 8; r++) sB[r][tid] = fmaxf(acc[r], 0.0f);
        __syncthreads();
    }
    {
        float acc[8];
        #pragma unroll
        for (int r = 0; r < 8; r++) acc[r] = b_n2[tid];
        #pragma unroll 4
        for (int k = 0; k < 256; k++) {
            float wv = W_n2[k * 256 + tid];
            #pragma unroll
            for (int r = 0; r < 8; r++) acc[r] += sB[r][k] * wv;
        }
        __syncthreads();
        #pragma unroll
        for (int r = 0; r < 8; r++) sA[r][tid] = fmaxf(acc[r], 0.0f);
        __syncthreads();
    }
    {
        float acc[8];
        #pragma unroll
        for (int r = 0; r < 8; r++) acc[r] = b_o1[tid];
        #pragma unroll
        for (int d = 0; d < 4; d++) {
            float wv = W_o1[d * 256 + tid];
            #pragma unroll
            for (int r = 0; r < 8; r++) acc[r] += sx[r][d] * wv;
        }
        #pragma unroll 4
        for (int k = 0; k < 256; k++) {
            float wv = W_o1[(4 + k) * 256 + tid];
            #pragma unroll
            for (int r = 0; r < 8; r++) acc[r] += sA[r][k] * wv;
        }
        __syncthreads();
        #pragma unroll
        for (int r = 0; r < 8; r++) sB[r][tid] = acc[r];
        __syncthreads();
    }
    if (tid < 32) {
        int r = tid >> 2, d = tid & 3;
        float acc = b_o[d];
        #pragma unroll 4
        for (int h = 0; h < 256; h++) acc += sB[r][h] * W_o[h * 4 + d];
        float m = acc;
        m = fmaxf(m, __shfl_xor_sync(0xffffffffu, m, 1));
        m = fmaxf(m, __shfl_xor_sync(0xffffffffu, m, 2));
        float e = expf(acc - m);
        float s = e;
        s += __shfl_xor_sync(0xffffffffu, s, 1);
        s += __shfl_xor_sync(0xffffffffu, s, 2);
        out[(row0 + r) * 4 + d] = acc - m - logf(s);
    }
}

// ---------------------------------------------------------------------------
// Launch
// ---------------------------------------------------------------------------
extern "C" void kernel_launch(void* const* d_in, const int* in_sizes, int n_in,
                              void* d_out, int out_size) {
    const float* x    = (const float*)d_in[0];
    const float* adj  = (const float*)d_in[1];
    const float* W_e1 = (const float*)d_in[2];
    const float* b_e1 = (const float*)d_in[3];
    const float* W_e2 = (const float*)d_in[4];
    const float* b_e2 = (const float*)d_in[5];
    const float* W_n1 = (const float*)d_in[6];
    const float* b_n1 = (const float*)d_in[7];
    const float* W_n2 = (const float*)d_in[8];
    const float* b_n2 = (const float*)d_in[9];
    const float* W_o1 = (const float*)d_in[10];
    const float* b_o1 = (const float*)d_in[11];
    const float* W_o  = (const float*)d_in[12];
    const float* b_o  = (const float*)d_in[13];
    float* out = (float*)d_out;

    prep_uv_kernel<<<(BB * NN * HH) / 256, 256>>>(x, W_e1, b_e1);
    wfrag_kernel<<<32, 256>>>(W_e2);
    adjT_kernel<<<dim3(16, 16, 4), dim3(32, 32)>>>(adj);
    edge_mma_kernel<<<BB * NN, 128>>>(b_e2);
    tail_kernel<<<(BB * NN) / 8, 256>>>(x, W_n1, b_n1, W_n2, b_n2,
                                        W_o1, b_o1, W_o, b_o, out);
}

// round 6
// speedup vs baseline: 14.9574x; 1.2238x over previous
#include <cuda_runtime.h>
#include <cuda_bf16.h>
#include <cuda_fp16.h>
#include <cstdint>
#include <math.h>

#define BB 4
#define NN 512
#define DD 4
#define HH 256

// ---------------------------------------------------------------------------
// Device scratch (allocation-free rule)
// ---------------------------------------------------------------------------
__device__ __align__(16) __half g_u16[BB * NN * HH];  // x[b,j]@W_e1[0:4]        (fp16)
__device__ __align__(16) __half g_v16[BB * NN * HH];  // x[b,i]@W_e1[4:8]+b_e1   (fp16)
__device__ __align__(16) float  g_agg[BB * NN * HH];
__device__ __align__(16) float  g_adjT[BB * NN * NN]; // adjT[b][j][i]
// W_e2 fp16 mma B-fragments, two k-steps per uint4:
// [t(8)][g(32)][lane(32)] -> uint4{ b0(s=2t), b1(s=2t), b0(s=2t+1), b1(s=2t+1) }
__device__ __align__(16) uint4 g_Wh[8 * 32 * 32];

// ---------------------------------------------------------------------------
// PTX wrappers (baseline sm_80-class; compile clean for compute_103)
// ---------------------------------------------------------------------------
__device__ __forceinline__ uint32_t smem_to_u32(const void* p) {
    uint32_t a;
    asm("{ .reg .u64 t; cvta.to.shared.u64 t, %1; cvt.u32.u64 %0, t; }" : "=r"(a) : "l"(p));
    return a;
}

__device__ __forceinline__ void ldm4(uint32_t r[4], uint32_t addr) {
    asm volatile("ldmatrix.sync.aligned.m8n8.x4.shared.b16 {%0,%1,%2,%3}, [%4];"
                 : "=r"(r[0]), "=r"(r[1]), "=r"(r[2]), "=r"(r[3]) : "r"(addr));
}

__device__ __forceinline__ void mma_f16(float c[4], const uint32_t a[4],
                                        uint32_t b0, uint32_t b1) {
    asm volatile(
        "mma.sync.aligned.m16n8k16.row.col.f32.f16.f16.f32 "
        "{%0,%1,%2,%3}, {%4,%5,%6,%7}, {%8,%9}, {%0,%1,%2,%3};"
        : "+f"(c[0]), "+f"(c[1]), "+f"(c[2]), "+f"(c[3])
        : "r"(a[0]), "r"(a[1]), "r"(a[2]), "r"(a[3]), "r"(b0), "r"(b1));
}

__device__ __forceinline__ uint32_t pack_h2(float a, float b) {
    __half2 h = __floats2half2_rn(a, b);
    return *(uint32_t*)&h;
}

__device__ __forceinline__ uint32_t hrelu2(uint32_t va, uint32_t ua) {
    __half2 s = __hadd2(*(const __half2*)&va, *(const __half2*)&ua);
    __half2 z = __float2half2_rn(0.0f);
    __half2 r = __hmax2(s, z);
    return *(uint32_t*)&r;
}

// Build one 32-half chunk (4 x uint4) of row ii into the swizzled A tile.
__device__ __forceinline__ void build_chunk(char* dstA, const __half* vrow,
                                            const __half* su, int ii, int kc) {
    const uint4* vp = (const uint4*)(vrow + kc);
    const uint4* up = (const uint4*)(su + kc);
    char* dst = dstA + ii * 512;
    const int sw = ii & 7;
    #pragma unroll
    for (int p = 0; p < 4; p++) {
        uint4 v = vp[p], u = up[p], o;
        o.x = hrelu2(v.x, u.x);
        o.y = hrelu2(v.y, u.y);
        o.z = hrelu2(v.z, u.z);
        o.w = hrelu2(v.w, u.w);
        int c16 = (kc >> 3) + p;
        *(uint4*)(dst + ((c16 ^ sw) << 4)) = o;
    }
}

// ---------------------------------------------------------------------------
// Kernel A: u, v in fp16
// ---------------------------------------------------------------------------
__global__ void prep_uv_kernel(const float* __restrict__ x,
                               const float* __restrict__ W_e1,
                               const float* __restrict__ b_e1) {
    int idx = blockIdx.x * blockDim.x + threadIdx.x;
    if (idx >= BB * NN * HH) return;
    int h  = idx & (HH - 1);
    int bn = idx >> 8;
    const float* xr = x + bn * DD;
    float su = 0.0f;
    float sv = b_e1[h];
    #pragma unroll
    for (int d = 0; d < DD; d++) {
        float xv = xr[d];
        su += xv * W_e1[d * HH + h];
        sv += xv * W_e1[(DD + d) * HH + h];
    }
    g_u16[idx] = __float2half_rn(su);
    g_v16[idx] = __float2half_rn(sv);
}

// ---------------------------------------------------------------------------
// Kernel W: pack W_e2 (fp16) into mma B-fragment layout, 2 k-steps per uint4
// ---------------------------------------------------------------------------
__global__ void wfrag_kernel(const float* __restrict__ W_e2) {
    int idx = blockIdx.x * blockDim.x + threadIdx.x;   // 8192
    if (idx >= 8 * 32 * 32) return;
    int lane = idx & 31;
    int g    = (idx >> 5) & 31;
    int t    = idx >> 10;
    int n  = g * 8 + (lane >> 2);
    int q  = lane & 3;
    int k0 = (2 * t) * 16 + q * 2;
    int k1 = (2 * t + 1) * 16 + q * 2;

    uint4 o;
    o.x = pack_h2(W_e2[(k0)     * HH + n], W_e2[(k0 + 1) * HH + n]);
    o.y = pack_h2(W_e2[(k0 + 8) * HH + n], W_e2[(k0 + 9) * HH + n]);
    o.z = pack_h2(W_e2[(k1)     * HH + n], W_e2[(k1 + 1) * HH + n]);
    o.w = pack_h2(W_e2[(k1 + 8) * HH + n], W_e2[(k1 + 9) * HH + n]);
    g_Wh[idx] = o;
}

// ---------------------------------------------------------------------------
// Kernel T: transpose adj -> adjT[b][j][i]
// ---------------------------------------------------------------------------
__global__ void adjT_kernel(const float* __restrict__ adj) {
    __shared__ float t[32][33];
    int b = blockIdx.z;
    int i0 = blockIdx.y * 32, j0 = blockIdx.x * 32;
    t[threadIdx.y][threadIdx.x] =
        adj[((size_t)b * NN + i0 + threadIdx.y) * NN + j0 + threadIdx.x];
    __syncthreads();
    g_adjT[((size_t)b * NN + j0 + threadIdx.y) * NN + i0 + threadIdx.x] =
        t[threadIdx.x][threadIdx.y];
}

// ---------------------------------------------------------------------------
// Kernel E: per (b,j) edge GEMM, fused bias+relu+adj-weighted i-reduction.
// 4 warps; warp tile 64(M) x 64(N); double-buffered A; build of iter+1
// interleaved into iter's mma t-loop (chunks at t=0..3).
// ---------------------------------------------------------------------------
__global__ __launch_bounds__(128, 2)
void edge_mma_kernel(const float* __restrict__ b_e2) {
    __shared__ __align__(16) __half s_u16[HH];
    __shared__ float s_b2[HH];
    __shared__ float s_adj[NN];
    __shared__ __align__(16) __half sA[2][64 * 256];

    const int bid  = blockIdx.x;          // b*512 + j
    const int b    = bid >> 9;
    const int tid  = threadIdx.x;
    const int warp = tid >> 5;            // owns cols [warp*64, +64)
    const int lane = tid & 31;
    const int rg   = lane >> 2;
    const int q    = lane & 3;
    const int hi4  = lane >> 4;

    if (tid < 32)
        ((uint4*)s_u16)[tid] = ((const uint4*)(g_u16 + (size_t)bid * HH))[tid];
    s_b2[tid]       = b_e2[tid];
    s_b2[tid + 128] = b_e2[tid + 128];
    {
        const float* adjrow = g_adjT + ((size_t)b * NN + (bid & (NN - 1))) * NN;
        #pragma unroll
        for (int p = 0; p < 4; p++) s_adj[tid + p * 128] = adjrow[tid + p * 128];
    }

    const uint32_t swb = (uint32_t)(lane & 7);

    // build mapping: row ii = tid>>1, 128-half k-range kb
    const int ii = tid >> 1;
    const int kb = (tid & 1) * 128;
    const __half* vbase = g_v16 + (size_t)b * NN * HH;

    __syncthreads();   // s_u16 ready for builders

    // ---- prologue: build iter 0 fully into buffer 0 ----
    {
        const __half* vrow = vbase + (size_t)ii * HH;
        #pragma unroll
        for (int c = 0; c < 4; c++)
            build_chunk((char*)sA[0], vrow, s_u16, ii, kb + c * 32);
    }
    __syncthreads();

    float partial[16];
    #pragma unroll
    for (int c = 0; c < 16; c++) partial[c] = 0.0f;

    #pragma unroll 1
    for (int iter = 0; iter < 8; iter++) {
        const uint32_t aB = smem_to_u32(sA[iter & 1]);
        char* nxtA = (char*)sA[(iter & 1) ^ 1];
        const uint32_t rbase = aB + (uint32_t)(lane & 15) * 512;
        const __half* vnext = vbase + (size_t)((iter + 1) * 64 + ii) * HH;

        float C[4][8][4];
        #pragma unroll
        for (int m = 0; m < 4; m++)
            #pragma unroll
            for (int j = 0; j < 8; j++)
                #pragma unroll
                for (int e = 0; e < 4; e++) C[m][j][e] = 0.0f;

        #pragma unroll 1
        for (int t = 0; t < 8; t++) {
            uint32_t a0[4][4], a1[4][4];
            uint32_t c0 = (uint32_t)(4 * t + hi4);
            #pragma unroll
            for (int m = 0; m < 4; m++) {
                uint32_t rb = rbase + (uint32_t)(m * 16) * 512;
                ldm4(a0[m], rb + (((c0)     ^ swb) << 4));
                ldm4(a1[m], rb + (((c0 + 2) ^ swb) << 4));
            }
            // interleave next-tile build (chunks at t=0..3)
            if (t < 4 && iter < 7)
                build_chunk(nxtA, vnext, s_u16, ii, kb + t * 32);

            const uint4* wp = g_Wh + ((t * 32) + warp * 8) * 32 + lane;
            #pragma unroll
            for (int j = 0; j < 8; j++) {
                uint4 wf = wp[j * 32];
                #pragma unroll
                for (int m = 0; m < 4; m++) {
                    mma_f16(C[m][j], a0[m], wf.x, wf.y);
                    mma_f16(C[m][j], a1[m], wf.z, wf.w);
                }
            }
        }

        // ---- epilogue: bias + relu, adj-weight, accumulate over i ----
        #pragma unroll
        for (int m = 0; m < 4; m++) {
            float aw0 = s_adj[iter * 64 + m * 16 + rg];
            float aw1 = s_adj[iter * 64 + m * 16 + rg + 8];
            #pragma unroll
            for (int j = 0; j < 8; j++) {
                float bb0 = s_b2[warp * 64 + j * 8 + q * 2];
                float bb1 = s_b2[warp * 64 + j * 8 + q * 2 + 1];
                partial[j*2+0] += aw0 * fmaxf(C[m][j][0] + bb0, 0.0f)
                                + aw1 * fmaxf(C[m][j][2] + bb0, 0.0f);
                partial[j*2+1] += aw0 * fmaxf(C[m][j][1] + bb1, 0.0f)
                                + aw1 * fmaxf(C[m][j][3] + bb1, 0.0f);
            }
        }
        __syncthreads();   // next buffer fully built; cur buffer free to overwrite
    }

    // ---- reduce over 8 row-groups (lanes stride 4); lanes 0-3 write ----
    #pragma unroll
    for (int c = 0; c < 16; c++) {
        float v = partial[c];
        v += __shfl_down_sync(0xffffffffu, v, 16);
        v += __shfl_down_sync(0xffffffffu, v, 8);
        v += __shfl_down_sync(0xffffffffu, v, 4);
        partial[c] = v;
    }
    if (lane < 4) {
        #pragma unroll
        for (int c = 0; c < 16; c++) {
            int col = warp * 64 + (c >> 1) * 8 + lane * 2 + (c & 1);
            g_agg[bid * HH + col] = partial[c];
        }
    }
}

// ---------------------------------------------------------------------------
// Kernel C: per-node MLP + log_softmax
// ---------------------------------------------------------------------------
__global__ __launch_bounds__(256, 4)
void tail_kernel(const float* __restrict__ x,
                 const float* __restrict__ W_n1, const float* __restrict__ b_n1,
                 const float* __restrict__ W_n2, const float* __restrict__ b_n2,
                 const float* __restrict__ W_o1, const float* __restrict__ b_o1,
                 const float* __restrict__ W_o,  const float* __restrict__ b_o,
                 float* __restrict__ out) {
    __shared__ float sA[8][256];
    __shared__ float sB[8][256];
    __shared__ float sx[8][4];

    const int row0 = blockIdx.x * 8;
    const int tid  = threadIdx.x;

    #pragma unroll
    for (int r = 0; r < 8; r++) sA[r][tid] = g_agg[(row0 + r) * HH + tid];
    if (tid < 32) sx[tid >> 2][tid & 3] = x[row0 * DD + tid];
    __syncthreads();

    {
        float acc[8];
        #pragma unroll
        for (int r = 0; r < 8; r++) acc[r] = b_n1[tid];
        #pragma unroll 4
        for (int k = 0; k < 256; k++) {
            float wv = W_n1[k * 256 + tid];
            #pragma unroll
            for (int r = 0; r < 8; r++) acc[r] += sA[r][k] * wv;
        }
        #pragma unroll
        for (int r = 0; r < 8; r++) sB[r][tid] = fmaxf(acc[r], 0.0f);
        __syncthreads();
    }
    {
        float acc[8];
        #pragma unroll
        for (int r = 0; r < 8; r++) acc[r] = b_n2[tid];
        #pragma unroll 4
        for (int k = 0; k < 256; k++) {
            float wv = W_n2[k * 256 + tid];
            #pragma unroll
            for (int r = 0; r < 8; r++) acc[r] += sB[r][k] * wv;
        }
        __syncthreads();
        #pragma unroll
        for (int r = 0; r < 8; r++) sA[r][tid] = fmaxf(acc[r], 0.0f);
        __syncthreads();
    }
    {
        float acc[8];
        #pragma unroll
        for (int r = 0; r < 8; r++) acc[r] = b_o1[tid];
        #pragma unroll
        for (int d = 0; d < 4; d++) {
            float wv = W_o1[d * 256 + tid];
            #pragma unroll
            for (int r = 0; r < 8; r++) acc[r] += sx[r][d] * wv;
        }
        #pragma unroll 4
        for (int k = 0; k < 256; k++) {
            float wv = W_o1[(4 + k) * 256 + tid];
            #pragma unroll
            for (int r = 0; r < 8; r++) acc[r] += sA[r][k] * wv;
        }
        __syncthreads();
        #pragma unroll
        for (int r = 0; r < 8; r++) sB[r][tid] = acc[r];
        __syncthreads();
    }
    if (tid < 32) {
        int r = tid >> 2, d = tid & 3;
        float acc = b_o[d];
        #pragma unroll 4
        for (int h = 0; h < 256; h++) acc += sB[r][h] * W_o[h * 4 + d];
        float m = acc;
        m = fmaxf(m, __shfl_xor_sync(0xffffffffu, m, 1));
        m = fmaxf(m, __shfl_xor_sync(0xffffffffu, m, 2));
        float e = expf(acc - m);
        float s = e;
        s += __shfl_xor_sync(0xffffffffu, s, 1);
        s += __shfl_xor_sync(0xffffffffu, s, 2);
        out[(row0 + r) * 4 + d] = acc - m - logf(s);
    }
}

// ---------------------------------------------------------------------------
// Launch
// ---------------------------------------------------------------------------
extern "C" void kernel_launch(void* const* d_in, const int* in_sizes, int n_in,
                              void* d_out, int out_size) {
    const float* x    = (const float*)d_in[0];
    const float* adj  = (const float*)d_in[1];
    const float* W_e1 = (const float*)d_in[2];
    const float* b_e1 = (const float*)d_in[3];
    const float* W_e2 = (const float*)d_in[4];
    const float* b_e2 = (const float*)d_in[5];
    const float* W_n1 = (const float*)d_in[6];
    const float* b_n1 = (const float*)d_in[7];
    const float* W_n2 = (const float*)d_in[8];
    const float* b_n2 = (const float*)d_in[9];
    const float* W_o1 = (const float*)d_in[10];
    const float* b_o1 = (const float*)d_in[11];
    const float* W_o  = (const float*)d_in[12];
    const float* b_o  = (const float*)d_in[13];
    float* out = (float*)d_out;

    prep_uv_kernel<<<(BB * NN * HH) / 256, 256>>>(x, W_e1, b_e1);
    wfrag_kernel<<<32, 256>>>(W_e2);
    adjT_kernel<<<dim3(16, 16, 4), dim3(32, 32)>>>(adj);
    edge_mma_kernel<<<BB * NN, 128>>>(b_e2);
    tail_kernel<<<(BB * NN) / 8, 256>>>(x, W_n1, b_n1, W_n2, b_n2,
                                        W_o1, b_o1, W_o, b_o, out);
}

// round 7
// speedup vs baseline: 17.7343x; 1.1857x over previous
#include <cuda_runtime.h>
#include <cuda_bf16.h>
#include <cuda_fp16.h>
#include <cstdint>
#include <math.h>

#define BB 4
#define NN 512
#define DD 4
#define HH 256

// V staging layout: row stride 296 halfs (592B), second 128-half chunk at +136 halfs
#define VSTRIDE 296
#define VHALF2  136

// ---------------------------------------------------------------------------
// Device scratch (allocation-free rule)
// ---------------------------------------------------------------------------
__device__ __align__(16) __half g_u16[BB * NN * HH];  // x[b,j]@W_e1[0:4]        (fp16)
__device__ __align__(16) __half g_v16[BB * NN * HH];  // x[b,i]@W_e1[4:8]+b_e1   (fp16)
__device__ __align__(16) float  g_agg[BB * NN * HH];
__device__ __align__(16) float  g_adjT[BB * NN * NN]; // adjT[b][j][i]
// W_e2 fp16 mma B-fragments, two k-steps per uint4:
// [t(8)][g(32)][lane(32)] -> uint4{ b0(s=2t), b1(s=2t), b0(s=2t+1), b1(s=2t+1) }
__device__ __align__(16) uint4 g_Wh[8 * 32 * 32];

// ---------------------------------------------------------------------------
// PTX wrappers (baseline sm_80-class; compile clean for compute_103)
// ---------------------------------------------------------------------------
__device__ __forceinline__ uint32_t smem_to_u32(const void* p) {
    uint32_t a;
    asm("{ .reg .u64 t; cvta.to.shared.u64 t, %1; cvt.u32.u64 %0, t; }" : "=r"(a) : "l"(p));
    return a;
}

__device__ __forceinline__ void ldm4(uint32_t r[4], uint32_t addr) {
    asm volatile("ldmatrix.sync.aligned.m8n8.x4.shared.b16 {%0,%1,%2,%3}, [%4];"
                 : "=r"(r[0]), "=r"(r[1]), "=r"(r[2]), "=r"(r[3]) : "r"(addr));
}

__device__ __forceinline__ void mma_f16(float c[4], const uint32_t a[4],
                                        uint32_t b0, uint32_t b1) {
    asm volatile(
        "mma.sync.aligned.m16n8k16.row.col.f32.f16.f16.f32 "
        "{%0,%1,%2,%3}, {%4,%5,%6,%7}, {%8,%9}, {%0,%1,%2,%3};"
        : "+f"(c[0]), "+f"(c[1]), "+f"(c[2]), "+f"(c[3])
        : "r"(a[0]), "r"(a[1]), "r"(a[2]), "r"(a[3]), "r"(b0), "r"(b1));
}

__device__ __forceinline__ uint32_t pack_h2(float a, float b) {
    __half2 h = __floats2half2_rn(a, b);
    return *(uint32_t*)&h;
}

__device__ __forceinline__ uint32_t hrelu2(uint32_t va, uint32_t ua) {
    __half2 s = __hadd2(*(const __half2*)&va, *(const __half2*)&ua);
    __half2 z = __float2half2_rn(0.0f);
    __half2 r = __hmax2(s, z);
    return *(uint32_t*)&r;
}

__device__ __forceinline__ void cp_async16(uint32_t dst, const void* src) {
    asm volatile("cp.async.cg.shared.global [%0], [%1], 16;" :: "r"(dst), "l"(src));
}

// ---------------------------------------------------------------------------
// Kernel A: u, v in fp16
// ---------------------------------------------------------------------------
__global__ void prep_uv_kernel(const float* __restrict__ x,
                               const float* __restrict__ W_e1,
                               const float* __restrict__ b_e1) {
    int idx = blockIdx.x * blockDim.x + threadIdx.x;
    if (idx >= BB * NN * HH) return;
    int h  = idx & (HH - 1);
    int bn = idx >> 8;
    const float* xr = x + bn * DD;
    float su = 0.0f;
    float sv = b_e1[h];
    #pragma unroll
    for (int d = 0; d < DD; d++) {
        float xv = xr[d];
        su += xv * W_e1[d * HH + h];
        sv += xv * W_e1[(DD + d) * HH + h];
    }
    g_u16[idx] = __float2half_rn(su);
    g_v16[idx] = __float2half_rn(sv);
}

// ---------------------------------------------------------------------------
// Kernel W: pack W_e2 (fp16) into mma B-fragment layout, 2 k-steps per uint4
// ---------------------------------------------------------------------------
__global__ void wfrag_kernel(const float* __restrict__ W_e2) {
    int idx = blockIdx.x * blockDim.x + threadIdx.x;   // 8192
    if (idx >= 8 * 32 * 32) return;
    int lane = idx & 31;
    int g    = (idx >> 5) & 31;
    int t    = idx >> 10;
    int n  = g * 8 + (lane >> 2);
    int q  = lane & 3;
    int k0 = (2 * t) * 16 + q * 2;
    int k1 = (2 * t + 1) * 16 + q * 2;

    uint4 o;
    o.x = pack_h2(W_e2[(k0)     * HH + n], W_e2[(k0 + 1) * HH + n]);
    o.y = pack_h2(W_e2[(k0 + 8) * HH + n], W_e2[(k0 + 9) * HH + n]);
    o.z = pack_h2(W_e2[(k1)     * HH + n], W_e2[(k1 + 1) * HH + n]);
    o.w = pack_h2(W_e2[(k1 + 8) * HH + n], W_e2[(k1 + 9) * HH + n]);
    g_Wh[idx] = o;
}

// ---------------------------------------------------------------------------
// Kernel T: transpose adj -> adjT[b][j][i]
// ---------------------------------------------------------------------------
__global__ void adjT_kernel(const float* __restrict__ adj) {
    __shared__ float t[32][33];
    int b = blockIdx.z;
    int i0 = blockIdx.y * 32, j0 = blockIdx.x * 32;
    t[threadIdx.y][threadIdx.x] =
        adj[((size_t)b * NN + i0 + threadIdx.y) * NN + j0 + threadIdx.x];
    __syncthreads();
    g_adjT[((size_t)b * NN + j0 + threadIdx.y) * NN + i0 + threadIdx.x] =
        t[threadIdx.x][threadIdx.y];
}

// ---------------------------------------------------------------------------
// Kernel E: per (b,j) edge GEMM, fused bias+relu+adj-weighted i-reduction.
// 4 warps; warp tile 64(M) x 64(N). A single-buffered; next v tile staged in
// smem via cp.async (issued at iter start, landed before the post-loop build).
// The mma t-loop touches only SMEM + L1-resident W fragments.
// ---------------------------------------------------------------------------
__global__ __launch_bounds__(128, 2)
void edge_mma_kernel(const float* __restrict__ b_e2) {
    __shared__ __align__(16) __half s_u16[HH];
    __shared__ float s_b2[HH];
    __shared__ float s_adj[NN];
    __shared__ __align__(16) __half sA[64 * 256];
    __shared__ __align__(16) __half sV[64 * VSTRIDE + 8];

    const int bid  = blockIdx.x;          // b*512 + j
    const int b    = bid >> 9;
    const int tid  = threadIdx.x;
    const int warp = tid >> 5;            // owns cols [warp*64, +64)
    const int lane = tid & 31;
    const int rg   = lane >> 2;
    const int q    = lane & 3;
    const int hi4  = lane >> 4;

    if (tid < 32)
        ((uint4*)s_u16)[tid] = ((const uint4*)(g_u16 + (size_t)bid * HH))[tid];
    s_b2[tid]       = b_e2[tid];
    s_b2[tid + 128] = b_e2[tid + 128];
    {
        const float* adjrow = g_adjT + ((size_t)b * NN + (bid & (NN - 1))) * NN;
        #pragma unroll
        for (int p = 0; p < 4; p++) s_adj[tid + p * 128] = adjrow[tid + p * 128];
    }

    const uint32_t swb   = (uint32_t)(lane & 7);
    const uint32_t svB   = smem_to_u32(sV);
    const __half*  vbase = g_v16 + (size_t)b * NN * HH;

    // cp.async per-thread constants: column chunk c = lane (fixed), rows warp+4p
    const uint32_t coff = (lane < 16) ? (uint32_t)(lane * 16)
                                      : (uint32_t)(272 + (lane - 16) * 16);
    const int csrc = lane * 8;            // halfs

    // build mapping: row ii = tid>>1, 128-half k-range kb
    const int ii = tid >> 1;
    const int kb = (tid & 1) * 128;
    const __half* vsrcS = sV + ii * VSTRIDE + ((tid & 1) ? VHALF2 : 0);
    const __half* usrc  = s_u16 + kb;
    char* adst = (char*)sA + ii * 512;
    const int sw = ii & 7;

    // ---- prologue: stage V(0), build A(0) ----
    {
        const __half* vg = vbase;
        #pragma unroll
        for (int p = 0; p < 16; p++) {
            int r = warp + p * 4;
            cp_async16(svB + (uint32_t)r * (VSTRIDE * 2) + coff, vg + (size_t)r * HH + csrc);
        }
        asm volatile("cp.async.commit_group;" ::: "memory");
        asm volatile("cp.async.wait_group 0;" ::: "memory");
        __syncthreads();
        #pragma unroll
        for (int p = 0; p < 16; p++) {
            uint4 v = ((const uint4*)vsrcS)[p];
            uint4 u = ((const uint4*)usrc)[p];
            uint4 o;
            o.x = hrelu2(v.x, u.x);
            o.y = hrelu2(v.y, u.y);
            o.z = hrelu2(v.z, u.z);
            o.w = hrelu2(v.w, u.w);
            int c16 = (kb >> 3) + p;
            *(uint4*)(adst + ((c16 ^ sw) << 4)) = o;
        }
    }
    __syncthreads();

    float partial[16];
    #pragma unroll
    for (int c = 0; c < 16; c++) partial[c] = 0.0f;

    #pragma unroll 1
    for (int iter = 0; iter < 8; iter++) {
        // ---- stage V(iter+1) (fire and forget) ----
        if (iter < 7) {
            const __half* vg = vbase + (size_t)((iter + 1) * 64) * HH;
            #pragma unroll
            for (int p = 0; p < 16; p++) {
                int r = warp + p * 4;
                cp_async16(svB + (uint32_t)r * (VSTRIDE * 2) + coff, vg + (size_t)r * HH + csrc);
            }
            asm volatile("cp.async.commit_group;" ::: "memory");
        }

        // ---- mma t-loop over A(iter): smem + L1 W-frags only ----
        const uint32_t rbase = smem_to_u32(sA) + (uint32_t)(lane & 15) * 512;
        float C[4][8][4];
        #pragma unroll
        for (int m = 0; m < 4; m++)
            #pragma unroll
            for (int j = 0; j < 8; j++)
                #pragma unroll
                for (int e = 0; e < 4; e++) C[m][j][e] = 0.0f;

        #pragma unroll 1
        for (int t = 0; t < 8; t++) {
            uint32_t a0[4][4], a1[4][4];
            uint32_t c0 = (uint32_t)(4 * t + hi4);
            #pragma unroll
            for (int m = 0; m < 4; m++) {
                uint32_t rb = rbase + (uint32_t)(m * 16) * 512;
                ldm4(a0[m], rb + (((c0)     ^ swb) << 4));
                ldm4(a1[m], rb + (((c0 + 2) ^ swb) << 4));
            }
            const uint4* wp = g_Wh + ((t * 32) + warp * 8) * 32 + lane;
            #pragma unroll
            for (int j = 0; j < 8; j++) {
                uint4 wf = wp[j * 32];
                #pragma unroll
                for (int m = 0; m < 4; m++) {
                    mma_f16(C[m][j], a0[m], wf.x, wf.y);
                    mma_f16(C[m][j], a1[m], wf.z, wf.w);
                }
            }
        }

        // ---- epilogue: bias + relu, adj-weight, accumulate over i ----
        #pragma unroll
        for (int m = 0; m < 4; m++) {
            float aw0 = s_adj[iter * 64 + m * 16 + rg];
            float aw1 = s_adj[iter * 64 + m * 16 + rg + 8];
            #pragma unroll
            for (int j = 0; j < 8; j++) {
                float bb0 = s_b2[warp * 64 + j * 8 + q * 2];
                float bb1 = s_b2[warp * 64 + j * 8 + q * 2 + 1];
                partial[j*2+0] += aw0 * fmaxf(C[m][j][0] + bb0, 0.0f)
                                + aw1 * fmaxf(C[m][j][2] + bb0, 0.0f);
                partial[j*2+1] += aw0 * fmaxf(C[m][j][1] + bb1, 0.0f)
                                + aw1 * fmaxf(C[m][j][3] + bb1, 0.0f);
            }
        }

        // ---- wait V(iter+1), rebuild A in place ----
        if (iter < 7) {
            asm volatile("cp.async.wait_group 0;" ::: "memory");
        }
        __syncthreads();   // A fully consumed by all warps + V arrival visible
        if (iter < 7) {
            #pragma unroll
            for (int p = 0; p < 16; p++) {
                uint4 v = ((const uint4*)vsrcS)[p];
                uint4 u = ((const uint4*)usrc)[p];
                uint4 o;
                o.x = hrelu2(v.x, u.x);
                o.y = hrelu2(v.y, u.y);
                o.z = hrelu2(v.z, u.z);
                o.w = hrelu2(v.w, u.w);
                int c16 = (kb >> 3) + p;
                *(uint4*)(adst + ((c16 ^ sw) << 4)) = o;
            }
            __syncthreads();   // A(iter+1) ready
        }
    }

    // ---- reduce over 8 row-groups (lanes stride 4); lanes 0-3 write ----
    #pragma unroll
    for (int c = 0; c < 16; c++) {
        float v = partial[c];
        v += __shfl_down_sync(0xffffffffu, v, 16);
        v += __shfl_down_sync(0xffffffffu, v, 8);
        v += __shfl_down_sync(0xffffffffu, v, 4);
        partial[c] = v;
    }
    if (lane < 4) {
        #pragma unroll
        for (int c = 0; c < 16; c++) {
            int col = warp * 64 + (c >> 1) * 8 + lane * 2 + (c & 1);
            g_agg[bid * HH + col] = partial[c];
        }
    }
}

// ---------------------------------------------------------------------------
// Kernel C: per-node MLP + log_softmax
// ---------------------------------------------------------------------------
__global__ __launch_bounds__(256, 4)
void tail_kernel(const float* __restrict__ x,
                 const float* __restrict__ W_n1, const float* __restrict__ b_n1,
                 const float* __restrict__ W_n2, const float* __restrict__ b_n2,
                 const float* __restrict__ W_o1, const float* __restrict__ b_o1,
                 const float* __restrict__ W_o,  const float* __restrict__ b_o,
                 float* __restrict__ out) {
    __shared__ float sA[8][256];
    __shared__ float sB[8][256];
    __shared__ float sx[8][4];

    const int row0 = blockIdx.x * 8;
    const int tid  = threadIdx.x;

    #pragma unroll
    for (int r = 0; r < 8; r++) sA[r][tid] = g_agg[(row0 + r) * HH + tid];
    if (tid < 32) sx[tid >> 2][tid & 3] = x[row0 * DD + tid];
    __syncthreads();

    {
        float acc[8];
        #pragma unroll
        for (int r = 0; r < 8; r++) acc[r] = b_n1[tid];
        #pragma unroll 4
        for (int k = 0; k < 256; k++) {
            float wv = W_n1[k * 256 + tid];
            #pragma unroll
            for (int r = 0; r < 8; r++) acc[r] += sA[r][k] * wv;
        }
        #pragma unroll
        for (int r = 0; r < 8; r++) sB[r][tid] = fmaxf(acc[r], 0.0f);
        __syncthreads();
    }
    {
        float acc[8];
        #pragma unroll
        for (int r = 0; r < 8; r++) acc[r] = b_n2[tid];
        #pragma unroll 4
        for (int k = 0; k < 256; k++) {
            float wv = W_n2[k * 256 + tid];
            #pragma unroll
            for (int r = 0; r < 8; r++) acc[r] += sB[r][k] * wv;
        }
        __syncthreads();
        #pragma unroll
        for (int r = 0; r < 8; r++) sA[r][tid] = fmaxf(acc[r], 0.0f);
        __syncthreads();
    }
    {
        float acc[8];
        #pragma unroll
        for (int r = 0; r < 8; r++) acc[r] = b_o1[tid];
        #pragma unroll
        for (int d = 0; d < 4; d++) {
            float wv = W_o1[d * 256 + tid];
            #pragma unroll
            for (int r = 0; r < 8; r++) acc[r] += sx[r][d] * wv;
        }
        #pragma unroll 4
        for (int k = 0; k < 256; k++) {
            float wv = W_o1[(4 + k) * 256 + tid];
            #pragma unroll
            for (int r = 0; r < 8; r++) acc[r] += sA[r][k] * wv;
        }
        __syncthreads();
        #pragma unroll
        for (int r = 0; r < 8; r++) sB[r][tid] = acc[r];
        __syncthreads();
    }
    if (tid < 32) {
        int r = tid >> 2, d = tid & 3;
        float acc = b_o[d];
        #pragma unroll 4
        for (int h = 0; h < 256; h++) acc += sB[r][h] * W_o[h * 4 + d];
        float m = acc;
        m = fmaxf(m, __shfl_xor_sync(0xffffffffu, m, 1));
        m = fmaxf(m, __shfl_xor_sync(0xffffffffu, m, 2));
        float e = expf(acc - m);
        float s = e;
        s += __shfl_xor_sync(0xffffffffu, s, 1);
        s += __shfl_xor_sync(0xffffffffu, s, 2);
        out[(row0 + r) * 4 + d] = acc - m - logf(s);
    }
}

// ---------------------------------------------------------------------------
// Launch
// ---------------------------------------------------------------------------
extern "C" void kernel_launch(void* const* d_in, const int* in_sizes, int n_in,
                              void* d_out, int out_size) {
    const float* x    = (const float*)d_in[0];
    const float* adj  = (const float*)d_in[1];
    const float* W_e1 = (const float*)d_in[2];
    const float* b_e1 = (const float*)d_in[3];
    const float* W_e2 = (const float*)d_in[4];
    const float* b_e2 = (const float*)d_in[5];
    const float* W_n1 = (const float*)d_in[6];
    const float* b_n1 = (const float*)d_in[7];
    const float* W_n2 = (const float*)d_in[8];
    const float* b_n2 = (const float*)d_in[9];
    const float* W_o1 = (const float*)d_in[10];
    const float* b_o1 = (const float*)d_in[11];
    const float* W_o  = (const float*)d_in[12];
    const float* b_o  = (const float*)d_in[13];
    float* out = (float*)d_out;

    prep_uv_kernel<<<(BB * NN * HH) / 256, 256>>>(x, W_e1, b_e1);
    wfrag_kernel<<<32, 256>>>(W_e2);
    adjT_kernel<<<dim3(16, 16, 4), dim3(32, 32)>>>(adj);
    edge_mma_kernel<<<BB * NN, 128>>>(b_e2);
    tail_kernel<<<(BB * NN) / 8, 256>>>(x, W_n1, b_n1, W_n2, b_n2,
                                        W_o1, b_o1, W_o, b_o, out);
}